// round 2
// baseline (speedup 1.0000x reference)
#include <cuda_runtime.h>
#include <stdint.h>

#define T_STEPS 128
#define BATCH   64
#define IN_DIM  512
#define H       1024
#define NE      819          /* int(1024*0.8) excitatory units */
#define NL      3
#define KMAX    2048
#define KSLICE  256
#define NKC     8
#define NBLOCKS 128
#define NTHREADS 256
#define ALPHA   0.2f

// ---------------- device scratch (static, allocation-free) ----------------
__device__ float g_Wc[NL * KMAX * H];            // combined |W| with Dale sign folded, [j][k][i]
__device__ float g_xinT[T_STEPS * IN_DIM * BATCH]; // inputs transposed [t][k][b]
__device__ float g_h [NL * H * BATCH];           // raw hidden, [j][k][b]
__device__ float g_hm[NL * H * BATCH];           // e-masked hidden, [j][k][b]
__device__ float g_v [NL * BATCH * H];           // leaky state, [j][b][n]
__device__ float g_part[NKC * BATCH * H];        // split-K partials [kc][b][n]
__device__ unsigned g_bar_count;
__device__ unsigned g_bar_gen;

// ---------------- helpers ----------------
__device__ __forceinline__ unsigned long long pack2(float f) {
    unsigned long long r; unsigned u = __float_as_uint(f);
    asm("mov.b64 %0, {%1, %1};" : "=l"(r) : "r"(u));
    return r;
}
__device__ __forceinline__ unsigned long long fma2(unsigned long long a,
                                                   unsigned long long b,
                                                   unsigned long long c) {
    unsigned long long d;
    asm("fma.rn.f32x2 %0, %1, %2, %3;" : "=l"(d) : "l"(a), "l"(b), "l"(c));
    return d;
}

__device__ __forceinline__ void grid_sync(unsigned &gen) {
    __syncthreads();
    if (threadIdx.x == 0) {
        __threadfence();                          // publish my writes (gpu scope -> L1 inval)
        unsigned next = gen + 1;
        unsigned tick = atomicAdd(&g_bar_count, 1u);
        if (tick == NBLOCKS - 1) {
            g_bar_count = 0;
            __threadfence();
            *(volatile unsigned *)&g_bar_gen = next;   // release
        } else {
            while (*(volatile unsigned *)&g_bar_gen != next) {}
            __threadfence();                      // acquire: invalidate stale L1 lines
        }
    }
    __syncthreads();
    gen++;
}

// ---------------- preprocessing kernels ----------------
__global__ void k_prep_weights(const float* __restrict__ Win0,
                               const float* __restrict__ Win1,
                               const float* __restrict__ Win2,
                               const float* __restrict__ Wrec) {
    int idx = blockIdx.x * blockDim.x + threadIdx.x;
    if (idx >= NL * KMAX * H) return;
    int j = idx / (KMAX * H);
    int r = idx - j * (KMAX * H);
    int k = r >> 10;
    int i = r & (H - 1);
    float v = 0.f;
    if (j == 0) {
        if (k < IN_DIM) {
            v = fabsf(Win0[i * IN_DIM + k]);
        } else if (k < IN_DIM + H) {
            int kk = k - IN_DIM;
            v = fabsf(Wrec[(size_t)i * H + kk]);
            if (kk >= NE) v = -v;
        } // else: zero pad (kc 6,7 never computed anyway)
    } else {
        const float* Wi = (j == 1) ? Win1 : Win2;
        if (k < H) {
            v = fabsf(Wi[(size_t)i * H + k]);
        } else {
            int kk = k - H;
            v = fabsf(Wrec[((size_t)j * H + i) * H + kk]);
            if (kk >= NE) v = -v;
        }
    }
    g_Wc[idx] = v;
}

__global__ void k_transpose_inputs(const float* __restrict__ inputs) {
    int idx = blockIdx.x * blockDim.x + threadIdx.x;
    if (idx >= T_STEPS * IN_DIM * BATCH) return;
    int b = idx & (BATCH - 1);
    int k = (idx >> 6) & (IN_DIM - 1);
    int t = idx >> 15;                 // 512*64 = 2^15
    g_xinT[idx] = inputs[((size_t)t * BATCH + b) * IN_DIM + k];
}

__global__ void k_init(const float* __restrict__ hid0, float* __restrict__ out_hid) {
    int idx = blockIdx.x * blockDim.x + threadIdx.x;
    if (idx >= NL * H * BATCH) return;
    int b = idx & (BATCH - 1);
    int k = (idx >> 6) & (H - 1);
    int j = idx >> 16;                 // 1024*64 = 2^16
    float h0 = hid0[(size_t)b * H + k];
    g_h[idx]  = h0;
    g_hm[idx] = (k < NE) ? h0 : 0.f;
    g_v[idx]  = 0.f;                   // [j][b][n] layout, but zero is layout-agnostic
    // all_hiddens[j][0][b][k] = h0
    out_hid[((size_t)j * (T_STEPS + 1) * BATCH + b) * H + k] = h0;
    if (idx == 0) { g_bar_count = 0; g_bar_gen = 0; }
}

// ---------------- main persistent kernel ----------------
__global__ void __launch_bounds__(NTHREADS, 1)
k_main(const float* __restrict__ bias, float* __restrict__ out_y, float* __restrict__ out_hid) {
    extern __shared__ float xs[];      // 256 x 64 floats (64 KB), k-major activation tile
    const int bk   = blockIdx.x;
    const int tid  = threadIdx.x;
    const int lane = tid & 31;
    const int w    = tid >> 5;         // warp id, also phase-B row id (0..7)
    // phase A mapping: 16 neuron-groups x 8 k-chunks
    const int ng    = bk & 15;
    const int kc    = bk >> 4;
    const int nwarp = w & 1;           // 2 neuron-warps
    const int bg    = w >> 1;          // 4 batch-groups of 16
    const int nA    = ng * 64 + nwarp * 32 + lane;
    // phase B mapping: 32 n-tiles x 4 b-tiles
    const int n0 = (bk & 31) << 5;
    const int b0 = (bk >> 5) << 4;

    unsigned gen = 0;

    for (int t = 0; t < T_STEPS; t++) {
        for (int j = 0; j < NL; j++) {
            const int nkc = (j == 0) ? 6 : 8;

            // ---------------- Phase A: partial GEMM for this (ng, kc) ----------------
            if (kc < nkc) {
                const float* xsrc;
                if (j == 0) {
                    xsrc = (kc < 2)
                         ? (g_xinT + ((size_t)t * IN_DIM + kc * KSLICE) * BATCH)
                         : (g_h    + ((size_t)(kc - 2) * KSLICE) * BATCH);          // layer 0 recurrent
                } else {
                    xsrc = (kc < 4)
                         ? (g_hm + ((size_t)(j - 1) * H + kc * KSLICE) * BATCH)     // feedforward (masked)
                         : (g_h  + ((size_t)j * H + (kc - 4) * KSLICE) * BATCH);    // recurrent (raw)
                }
                // stage 64 KB activation slab into smem (same k-major layout)
                {
                    const float4* s4 = (const float4*)xsrc;
                    float4* d4 = (float4*)xs;
                    #pragma unroll
                    for (int i = 0; i < 16; i++) d4[tid + i * NTHREADS] = s4[tid + i * NTHREADS];
                }
                __syncthreads();

                unsigned long long acc[8];
                #pragma unroll
                for (int p = 0; p < 8; p++) acc[p] = 0ull;

                const float* wb = g_Wc + ((size_t)j * KMAX + (size_t)kc * KSLICE) * H + nA;
                const ulonglong2* xbase = reinterpret_cast<const ulonglong2*>(xs + bg * 16);

                #pragma unroll 1
                for (int kk = 0; kk < KSLICE; kk += 8) {
                    float wreg[8];
                    #pragma unroll
                    for (int u = 0; u < 8; u++) wreg[u] = wb[(size_t)(kk + u) * H];
                    #pragma unroll
                    for (int u = 0; u < 8; u++) {
                        unsigned long long wp = pack2(wreg[u]);
                        const ulonglong2* xr = xbase + (size_t)(kk + u) * 16; // 64 floats/row
                        ulonglong2 q0 = xr[0], q1 = xr[1], q2 = xr[2], q3 = xr[3];
                        acc[0] = fma2(q0.x, wp, acc[0]);
                        acc[1] = fma2(q0.y, wp, acc[1]);
                        acc[2] = fma2(q1.x, wp, acc[2]);
                        acc[3] = fma2(q1.y, wp, acc[3]);
                        acc[4] = fma2(q2.x, wp, acc[4]);
                        acc[5] = fma2(q2.y, wp, acc[5]);
                        acc[6] = fma2(q3.x, wp, acc[6]);
                        acc[7] = fma2(q3.y, wp, acc[7]);
                    }
                }
                // write partials: g_part[kc][b][n]
                float* pp = g_part + ((size_t)kc * BATCH + bg * 16) * H + nA;
                #pragma unroll
                for (int p = 0; p < 8; p++) {
                    uint2 u2 = *reinterpret_cast<uint2*>(&acc[p]);
                    pp[(size_t)(2 * p)     * H] = __uint_as_float(u2.x);
                    pp[(size_t)(2 * p + 1) * H] = __uint_as_float(u2.y);
                }
            }
            grid_sync(gen);

            // ---------------- Phase B: reduce + leaky/ReLU update + outputs ----------------
            {
                #pragma unroll
                for (int q = 0; q < 2; q++) {
                    int b  = b0 + w + q * 8;
                    int nn = n0 + lane;
                    float s = bias[j * H + nn];
                    for (int c = 0; c < nkc; c++)
                        s += g_part[((size_t)c * BATCH + b) * H + nn];
                    size_t vidx = ((size_t)j * BATCH + b) * H + nn;
                    float v = (1.0f - ALPHA) * g_v[vidx] + ALPHA * s;
                    g_v[vidx] = v;
                    float h = fmaxf(v, 0.f);
                    out_hid[(((size_t)j * (T_STEPS + 1) + (t + 1)) * BATCH + b) * H + nn] = h;
                    if (j == 2)
                        out_y[((size_t)t * BATCH + b) * H + nn] = (nn < NE) ? h : 0.f;
                    xs[lane * 17 + (w + q * 8)] = h;  // small padded transpose tile
                }
                __syncthreads();
                #pragma unroll
                for (int q = 0; q < 2; q++) {
                    int idx = tid + q * NTHREADS;      // 0..511 over 32n x 16b tile
                    int nn = idx >> 4, bb = idx & 15;
                    float h = xs[nn * 17 + bb];
                    size_t hidx = ((size_t)j * H + n0 + nn) * BATCH + b0 + bb;
                    g_h[hidx]  = h;
                    g_hm[hidx] = ((n0 + nn) < NE) ? h : 0.f;
                }
            }
            grid_sync(gen);
        }
    }
}

// ---------------- host entry ----------------
extern "C" void kernel_launch(void* const* d_in, const int* in_sizes, int n_in,
                              void* d_out, int out_size) {
    const float* inputs = (const float*)d_in[0];   // [128,64,512]
    const float* hid0   = (const float*)d_in[1];   // [1,64,1024]
    const float* Win0   = (const float*)d_in[2];   // [1024,512]
    const float* Win1   = (const float*)d_in[3];   // [1024,1024]
    const float* Win2   = (const float*)d_in[4];   // [1024,1024]
    const float* Wrec   = (const float*)d_in[5];   // [3,1024,1024]
    const float* bias   = (const float*)d_in[6];   // [3,1024]

    float* out_y   = (float*)d_out;                             // [128,64,1024]
    float* out_hid = (float*)d_out + (size_t)T_STEPS * BATCH * H; // [3,129,64,1024]

    cudaFuncSetAttribute(k_main, cudaFuncAttributeMaxDynamicSharedMemorySize, 65536);

    {
        int n = NL * KMAX * H;
        k_prep_weights<<<(n + 255) / 256, 256>>>(Win0, Win1, Win2, Wrec);
    }
    {
        int n = T_STEPS * IN_DIM * BATCH;
        k_transpose_inputs<<<(n + 255) / 256, 256>>>(inputs);
    }
    {
        int n = NL * H * BATCH;
        k_init<<<(n + 255) / 256, 256>>>(hid0, out_hid);
    }
    k_main<<<NBLOCKS, NTHREADS, 65536>>>(bias, out_y, out_hid);
}

// round 3
// speedup vs baseline: 1.1929x; 1.1929x over previous
#include <cuda_runtime.h>
#include <stdint.h>

#define T_STEPS 128
#define BATCH   64
#define IN_DIM  512
#define H       1024
#define NE      819          /* int(1024*0.8) excitatory units */
#define NL      3
#define KMAX    2048
#define KSLICE  256
#define NKC     16           /* 16 partial slices of 128 k each */
#define NBLOCKS 128
#define NTHREADS 256
#define ALPHA   0.2f

// ---------------- device scratch (static, allocation-free) ----------------
__device__ float g_Wc[NL * KMAX * H + 16 * H];   // combined |W| w/ Dale sign, [j][k][i], + pad rows
__device__ float g_xinT[T_STEPS * IN_DIM * BATCH]; // inputs transposed [t][k][b]
__device__ float g_h [NL * H * BATCH];           // raw hidden, [j][k][b]
__device__ float g_hm[NL * H * BATCH];           // e-masked hidden, [j][k][b]
__device__ float g_v [NL * BATCH * H];           // leaky state, [j][b][n]
__device__ float g_part[NKC * BATCH * H];        // split-K partials [kcc][b][n]
__device__ unsigned g_bar_count;
__device__ unsigned g_bar_gen;

// ---------------- helpers ----------------
__device__ __forceinline__ unsigned long long pack2(float f) {
    unsigned long long r; unsigned u = __float_as_uint(f);
    asm("mov.b64 %0, {%1, %1};" : "=l"(r) : "r"(u));
    return r;
}
__device__ __forceinline__ unsigned long long fma2(unsigned long long a,
                                                   unsigned long long b,
                                                   unsigned long long c) {
    unsigned long long d;
    asm("fma.rn.f32x2 %0, %1, %2, %3;" : "=l"(d) : "l"(a), "l"(b), "l"(c));
    return d;
}

__device__ __forceinline__ void grid_sync(unsigned &gen) {
    __syncthreads();
    if (threadIdx.x == 0) {
        __threadfence();                          // publish my writes (gpu scope)
        unsigned next = gen + 1;
        unsigned tick = atomicAdd(&g_bar_count, 1u);
        if (tick == NBLOCKS - 1) {
            g_bar_count = 0;
            __threadfence();
            *(volatile unsigned *)&g_bar_gen = next;   // release
        } else {
            while (*(volatile unsigned *)&g_bar_gen != next) {}
            __threadfence();                      // acquire
        }
    }
    __syncthreads();
    gen++;
}

// ---------------- preprocessing kernels ----------------
__global__ void k_prep_weights(const float* __restrict__ Win0,
                               const float* __restrict__ Win1,
                               const float* __restrict__ Win2,
                               const float* __restrict__ Wrec) {
    int idx = blockIdx.x * blockDim.x + threadIdx.x;
    if (idx >= NL * KMAX * H + 16 * H) return;
    if (idx >= NL * KMAX * H) { g_Wc[idx] = 0.f; return; }   // pad rows
    int j = idx / (KMAX * H);
    int r = idx - j * (KMAX * H);
    int k = r >> 10;
    int i = r & (H - 1);
    float v = 0.f;
    if (j == 0) {
        if (k < IN_DIM) {
            v = fabsf(Win0[i * IN_DIM + k]);
        } else if (k < IN_DIM + H) {
            int kk = k - IN_DIM;
            v = fabsf(Wrec[(size_t)i * H + kk]);
            if (kk >= NE) v = -v;
        }
    } else {
        const float* Wi = (j == 1) ? Win1 : Win2;
        if (k < H) {
            v = fabsf(Wi[(size_t)i * H + k]);
        } else {
            int kk = k - H;
            v = fabsf(Wrec[((size_t)j * H + i) * H + kk]);
            if (kk >= NE) v = -v;
        }
    }
    g_Wc[idx] = v;
}

__global__ void k_transpose_inputs(const float* __restrict__ inputs) {
    int idx = blockIdx.x * blockDim.x + threadIdx.x;
    if (idx >= T_STEPS * IN_DIM * BATCH) return;
    int b = idx & (BATCH - 1);
    int k = (idx >> 6) & (IN_DIM - 1);
    int t = idx >> 15;
    g_xinT[idx] = inputs[((size_t)t * BATCH + b) * IN_DIM + k];
}

__global__ void k_init(const float* __restrict__ hid0, float* __restrict__ out_hid) {
    int idx = blockIdx.x * blockDim.x + threadIdx.x;
    if (idx >= NL * H * BATCH) return;
    int b = idx & (BATCH - 1);
    int k = (idx >> 6) & (H - 1);
    int j = idx >> 16;
    float h0 = hid0[(size_t)b * H + k];
    g_h[idx]  = h0;
    g_hm[idx] = (k < NE) ? h0 : 0.f;
    g_v[idx]  = 0.f;
    out_hid[((size_t)j * (T_STEPS + 1) * BATCH + b) * H + k] = h0;
    if (idx == 0) { g_bar_count = 0; g_bar_gen = 0; }
}

// ---------------- main persistent kernel ----------------
__global__ void __launch_bounds__(NTHREADS, 1)
k_main(const float* __restrict__ bias, float* __restrict__ out_y, float* __restrict__ out_hid) {
    extern __shared__ float xs[];      // 256 x 64 floats (64 KB), k-major activation tile
    const int bk   = blockIdx.x;
    const int tid  = threadIdx.x;
    const int lane = tid & 31;
    const int w    = tid >> 5;         // warp id (0..7)
    // phase A mapping: 16 neuron-groups x 8 k-chunks (256 k each)
    const int ng   = bk & 15;
    const int kc   = bk >> 4;
    const int sk   = w & 1;            // sub-k half (128 k)
    const int bg   = w >> 1;           // 4 batch-groups of 16
    const int nA   = ng * 64 + lane;   // neuron 0; neuron 1 = nA + 32
    // phase B mapping: 32 n-tiles x 4 b-tiles
    const int n0 = (bk & 31) << 5;
    const int b0 = (bk >> 5) << 4;

    unsigned gen = 0;

    for (int t = 0; t < T_STEPS; t++) {
        for (int j = 0; j < NL; j++) {
            const int nkc = (j == 0) ? 6 : 8;

            // ---------------- Phase A ----------------
            if (kc < nkc) {
                // weight base for this warp's sub-k half
                const float* wb0 = g_Wc + ((size_t)j * KMAX + (size_t)kc * KSLICE + sk * 128) * H + nA;

                // issue initial weight prefetch BEFORE staging (overlaps LDG latency)
                float wa[16], wbuf[16];
                #pragma unroll
                for (int u = 0; u < 8; u++) {
                    wa[u]     = wb0[(size_t)u * H];
                    wa[8 + u] = wb0[(size_t)u * H + 32];
                }

                const float* xsrc;
                if (j == 0) {
                    xsrc = (kc < 2)
                         ? (g_xinT + ((size_t)t * IN_DIM + kc * KSLICE) * BATCH)
                         : (g_h    + ((size_t)(kc - 2) * KSLICE) * BATCH);
                } else {
                    xsrc = (kc < 4)
                         ? (g_hm + ((size_t)(j - 1) * H + kc * KSLICE) * BATCH)
                         : (g_h  + ((size_t)j * H + (kc - 4) * KSLICE) * BATCH);
                }
                {
                    const float4* s4 = (const float4*)xsrc;
                    float4* d4 = (float4*)xs;
                    #pragma unroll
                    for (int i = 0; i < 16; i++) d4[tid + i * NTHREADS] = s4[tid + i * NTHREADS];
                }
                __syncthreads();

                unsigned long long acc0[8], acc1[8];
                #pragma unroll
                for (int p = 0; p < 8; p++) { acc0[p] = 0ull; acc1[p] = 0ull; }

                const ulonglong2* xbase =
                    reinterpret_cast<const ulonglong2*>(xs + (size_t)(sk * 128) * 64 + bg * 16);

                #pragma unroll 1
                for (int kk = 0; kk < 128; kk += 16) {
                    // prefetch second half (kk+8 .. kk+15)
                    {
                        const float* wp = wb0 + (size_t)(kk + 8) * H;
                        #pragma unroll
                        for (int u = 0; u < 8; u++) {
                            wbuf[u]     = wp[(size_t)u * H];
                            wbuf[8 + u] = wp[(size_t)u * H + 32];
                        }
                    }
                    // compute first half with wa
                    #pragma unroll
                    for (int u = 0; u < 8; u++) {
                        const ulonglong2* xr = xbase + (size_t)(kk + u) * 16;
                        ulonglong2 q0 = xr[0], q1 = xr[1], q2 = xr[2], q3 = xr[3];
                        unsigned long long w0 = pack2(wa[u]);
                        unsigned long long w1 = pack2(wa[8 + u]);
                        acc0[0] = fma2(q0.x, w0, acc0[0]);  acc1[0] = fma2(q0.x, w1, acc1[0]);
                        acc0[1] = fma2(q0.y, w0, acc0[1]);  acc1[1] = fma2(q0.y, w1, acc1[1]);
                        acc0[2] = fma2(q1.x, w0, acc0[2]);  acc1[2] = fma2(q1.x, w1, acc1[2]);
                        acc0[3] = fma2(q1.y, w0, acc0[3]);  acc1[3] = fma2(q1.y, w1, acc1[3]);
                        acc0[4] = fma2(q2.x, w0, acc0[4]);  acc1[4] = fma2(q2.x, w1, acc1[4]);
                        acc0[5] = fma2(q2.y, w0, acc0[5]);  acc1[5] = fma2(q2.y, w1, acc1[5]);
                        acc0[6] = fma2(q3.x, w0, acc0[6]);  acc1[6] = fma2(q3.x, w1, acc1[6]);
                        acc0[7] = fma2(q3.y, w0, acc0[7]);  acc1[7] = fma2(q3.y, w1, acc1[7]);
                    }
                    // prefetch next first half (kk+16 .. kk+23); pad rows make tail safe
                    {
                        const float* wp = wb0 + (size_t)(kk + 16) * H;
                        #pragma unroll
                        for (int u = 0; u < 8; u++) {
                            wa[u]     = wp[(size_t)u * H];
                            wa[8 + u] = wp[(size_t)u * H + 32];
                        }
                    }
                    // compute second half with wbuf
                    #pragma unroll
                    for (int u = 0; u < 8; u++) {
                        const ulonglong2* xr = xbase + (size_t)(kk + 8 + u) * 16;
                        ulonglong2 q0 = xr[0], q1 = xr[1], q2 = xr[2], q3 = xr[3];
                        unsigned long long w0 = pack2(wbuf[u]);
                        unsigned long long w1 = pack2(wbuf[8 + u]);
                        acc0[0] = fma2(q0.x, w0, acc0[0]);  acc1[0] = fma2(q0.x, w1, acc1[0]);
                        acc0[1] = fma2(q0.y, w0, acc0[1]);  acc1[1] = fma2(q0.y, w1, acc1[1]);
                        acc0[2] = fma2(q1.x, w0, acc0[2]);  acc1[2] = fma2(q1.x, w1, acc1[2]);
                        acc0[3] = fma2(q1.y, w0, acc0[3]);  acc1[3] = fma2(q1.y, w1, acc1[3]);
                        acc0[4] = fma2(q2.x, w0, acc0[4]);  acc1[4] = fma2(q2.x, w1, acc1[4]);
                        acc0[5] = fma2(q2.y, w0, acc0[5]);  acc1[5] = fma2(q2.y, w1, acc1[5]);
                        acc0[6] = fma2(q3.x, w0, acc0[6]);  acc1[6] = fma2(q3.x, w1, acc1[6]);
                        acc0[7] = fma2(q3.y, w0, acc0[7]);  acc1[7] = fma2(q3.y, w1, acc1[7]);
                    }
                }
                // write partials: slice kcc = kc*2 + sk, layout [kcc][b][n]
                const int kcc = kc * 2 + sk;
                float* pp = g_part + ((size_t)kcc * BATCH + bg * 16) * H + nA;
                #pragma unroll
                for (int p = 0; p < 8; p++) {
                    uint2 a0 = *reinterpret_cast<uint2*>(&acc0[p]);
                    uint2 a1 = *reinterpret_cast<uint2*>(&acc1[p]);
                    pp[(size_t)(2 * p)     * H]      = __uint_as_float(a0.x);
                    pp[(size_t)(2 * p + 1) * H]      = __uint_as_float(a0.y);
                    pp[(size_t)(2 * p)     * H + 32] = __uint_as_float(a1.x);
                    pp[(size_t)(2 * p + 1) * H + 32] = __uint_as_float(a1.y);
                }
            }
            grid_sync(gen);

            // ---------------- Phase B: reduce + leaky/ReLU update + outputs ----------------
            {
                const int nkcc = nkc * 2;
                #pragma unroll
                for (int q = 0; q < 2; q++) {
                    int b  = b0 + w + q * 8;
                    int nn = n0 + lane;
                    float s = bias[j * H + nn];
                    #pragma unroll 4
                    for (int c = 0; c < nkcc; c++)
                        s += g_part[((size_t)c * BATCH + b) * H + nn];
                    size_t vidx = ((size_t)j * BATCH + b) * H + nn;
                    float v = fmaf(1.0f - ALPHA, g_v[vidx], ALPHA * s);
                    g_v[vidx] = v;
                    float h = fmaxf(v, 0.f);
                    out_hid[(((size_t)j * (T_STEPS + 1) + (t + 1)) * BATCH + b) * H + nn] = h;
                    if (j == 2)
                        out_y[((size_t)t * BATCH + b) * H + nn] = (nn < NE) ? h : 0.f;
                    xs[lane * 17 + (w + q * 8)] = h;
                }
                __syncthreads();
                #pragma unroll
                for (int q = 0; q < 2; q++) {
                    int idx = tid + q * NTHREADS;
                    int nn = idx >> 4, bb = idx & 15;
                    float h = xs[nn * 17 + bb];
                    size_t hidx = ((size_t)j * H + n0 + nn) * BATCH + b0 + bb;
                    g_h[hidx]  = h;
                    g_hm[hidx] = ((n0 + nn) < NE) ? h : 0.f;
                }
            }
            grid_sync(gen);
        }
    }
}

// ---------------- host entry ----------------
extern "C" void kernel_launch(void* const* d_in, const int* in_sizes, int n_in,
                              void* d_out, int out_size) {
    const float* inputs = (const float*)d_in[0];   // [128,64,512]
    const float* hid0   = (const float*)d_in[1];   // [1,64,1024]
    const float* Win0   = (const float*)d_in[2];   // [1024,512]
    const float* Win1   = (const float*)d_in[3];   // [1024,1024]
    const float* Win2   = (const float*)d_in[4];   // [1024,1024]
    const float* Wrec   = (const float*)d_in[5];   // [3,1024,1024]
    const float* bias   = (const float*)d_in[6];   // [3,1024]

    float* out_y   = (float*)d_out;                               // [128,64,1024]
    float* out_hid = (float*)d_out + (size_t)T_STEPS * BATCH * H; // [3,129,64,1024]

    cudaFuncSetAttribute(k_main, cudaFuncAttributeMaxDynamicSharedMemorySize, 65536);

    {
        int n = NL * KMAX * H + 16 * H;
        k_prep_weights<<<(n + 255) / 256, 256>>>(Win0, Win1, Win2, Wrec);
    }
    {
        int n = T_STEPS * IN_DIM * BATCH;
        k_transpose_inputs<<<(n + 255) / 256, 256>>>(inputs);
    }
    {
        int n = NL * H * BATCH;
        k_init<<<(n + 255) / 256, 256>>>(hid0, out_hid);
    }
    k_main<<<NBLOCKS, NTHREADS, 65536>>>(bias, out_y, out_hid);
}